// round 9
// baseline (speedup 1.0000x reference)
#include <cuda_runtime.h>
#include <cuda_bf16.h>

// Shapes:
//   xq      [1, 8, 128, 128]  f32
//   xk      [1, 1, 128, 128]  f32
//   rot_mat [1, 128, 128, 128] f32
// out[n,s,d] = sum_h x[n,s,h] * R[s,h,d];  out = concat(xq_out, xk_out)

#define SEQ_LEN   128
#define HEAD_DIM  128
#define N_HEADS   9
#define THREADS   256
#define D_HALF    64          // d split across gridDim.y = 2
#define STAGES    4
#define STAGE_H   32          // h rows per stage

// Dynamic smem layout (bytes):
//   Rs   [STAGES][STAGE_H][D_HALF] f32 : 4*32*64*4  = 32768
//   xs2  [N_HEADS][HEAD_DIM] u64 (replicated {v,v}) = 9216
//   part [8][N_HEADS][D_HALF] f32                   = 18432
#define SMEM_RS    0
#define SMEM_XS    32768
#define SMEM_PART  (32768 + 9216)
#define SMEM_TOTAL (32768 + 9216 + 18432)   // 60416 B

__device__ __forceinline__ unsigned long long ffma2(unsigned long long a,
                                                    unsigned long long b,
                                                    unsigned long long c) {
    unsigned long long d;
    asm("fma.rn.f32x2 %0, %1, %2, %3;" : "=l"(d) : "l"(a), "l"(b), "l"(c));
    return d;
}

__global__ void __launch_bounds__(THREADS)
rotary_kernel(const float* __restrict__ xq,
              const float* __restrict__ xk,
              const float* __restrict__ R,
              float* __restrict__ out)
{
    extern __shared__ __align__(16) char smem[];
    float* Rs                 = reinterpret_cast<float*>(smem + SMEM_RS);
    unsigned long long* xs2   = reinterpret_cast<unsigned long long*>(smem + SMEM_XS);
    float* part               = reinterpret_cast<float*>(smem + SMEM_PART);

    const int s   = blockIdx.x;
    const int dh  = blockIdx.y;
    const int tid = threadIdx.x;

    // ---- 1) Issue ALL R cp.asyncs up front: 4 stages x 2 x 16B per thread ----
    const float4* __restrict__ R4 =
        reinterpret_cast<const float4*>(R + (size_t)s * HEAD_DIM * HEAD_DIM);
    const int c  = tid & 15;      // float4 col within the d-half (0..15)
    const int hl = tid >> 4;      // 0..15: row within stage (also +16)
    const unsigned rs_base = (unsigned)__cvta_generic_to_shared(Rs);

#pragma unroll
    for (int k = 0; k < STAGES; k++) {
        const float4* src0 = &R4[(k * STAGE_H + hl)      * 32 + dh * 16 + c];
        const float4* src1 = &R4[(k * STAGE_H + hl + 16) * 32 + dh * 16 + c];
        const unsigned dst0 = rs_base + (k * STAGE_H + hl)      * 256u + c * 16u;
        const unsigned dst1 = rs_base + (k * STAGE_H + hl + 16) * 256u + c * 16u;
        asm volatile("cp.async.cg.shared.global [%0], [%1], 16;\n" :: "r"(dst0), "l"(src0));
        asm volatile("cp.async.cg.shared.global [%0], [%1], 16;\n" :: "r"(dst1), "l"(src1));
        asm volatile("cp.async.commit_group;\n" ::);
    }

    // ---- 2) Stage x rows for this s (overlapped with cp.async flight) ----
    for (int idx = tid; idx < N_HEADS * HEAD_DIM; idx += THREADS) {
        const int n = idx >> 7;
        const int h = idx & 127;
        float v;
        if (n < 8)
            v = xq[n * (SEQ_LEN * HEAD_DIM) + s * HEAD_DIM + h];
        else
            v = xk[s * HEAD_DIM + h];
        const unsigned long long u = (unsigned long long)__float_as_uint(v);
        xs2[idx] = (u << 32) | u;   // replicated {v,v} for fma.rn.f32x2
    }

    // ---- 3) Compute: warp = (head-group, h-subrange), lane = (h-phase, d4col) ----
    const int lane   = tid & 31;
    const int w      = tid >> 5;
    const int ng     = w >> 2;          // 0: heads 0..4, 1: heads 5..8
    const int wsub   = w & 3;           // h-subrange within stage
    const int d4l    = lane & 15;       // float4 col (0..15) => d = 4*d4l..
    const int h_lane = lane >> 4;       // 0/1
    const int nbase  = ng * 5;
    const int NH     = ng ? 4 : 5;

    unsigned long long a0[5], a1[5];
#pragma unroll
    for (int j = 0; j < 5; j++) { a0[j] = 0ull; a1[j] = 0ull; }

#pragma unroll
    for (int k = 0; k < STAGES; k++) {
        if      (k == 0) asm volatile("cp.async.wait_group 3;\n" ::);
        else if (k == 1) asm volatile("cp.async.wait_group 2;\n" ::);
        else if (k == 2) asm volatile("cp.async.wait_group 1;\n" ::);
        else             asm volatile("cp.async.wait_group 0;\n" ::);
        __syncthreads();

#pragma unroll
        for (int i = 0; i < 4; i++) {
            const int hh = wsub * 8 + h_lane + 2 * i;   // row within stage
            const int hg = k * STAGE_H + hh;            // global h
            const ulonglong2 r =
                *reinterpret_cast<const ulonglong2*>(&Rs[(k * STAGE_H + hh) * D_HALF + d4l * 4]);
#pragma unroll
            for (int j = 0; j < 5; j++) {
                if (j < NH) {
                    const unsigned long long xv = xs2[(nbase + j) * HEAD_DIM + hg];
                    a0[j] = ffma2(xv, r.x, a0[j]);
                    a1[j] = ffma2(xv, r.y, a1[j]);
                }
            }
        }
    }

    // ---- 4) Write per-(h-phase) partials ----
    const int pidx = wsub * 2 + h_lane;   // 0..7
#pragma unroll
    for (int j = 0; j < 5; j++) {
        if (j < NH) {
            const float2 lo = *reinterpret_cast<const float2*>(&a0[j]);
            const float2 hi = *reinterpret_cast<const float2*>(&a1[j]);
            *reinterpret_cast<float4*>(&part[(pidx * N_HEADS + (nbase + j)) * D_HALF + d4l * 4]) =
                make_float4(lo.x, lo.y, hi.x, hi.y);
        }
    }
    __syncthreads();

    // ---- 5) Reduce 8 partials and store (coalesced over d) ----
    for (int idx = tid; idx < N_HEADS * D_HALF; idx += THREADS) {
        const int n = idx >> 6;          // idx / 64
        const int d = idx & 63;          // idx % 64
        float sum = 0.f;
#pragma unroll
        for (int p = 0; p < 8; p++)
            sum += part[(p * N_HEADS + n) * D_HALF + d];
        out[n * (SEQ_LEN * HEAD_DIM) + s * HEAD_DIM + dh * D_HALF + d] = sum;
    }
}

extern "C" void kernel_launch(void* const* d_in, const int* in_sizes, int n_in,
                              void* d_out, int out_size)
{
    const float* xq = (const float*)d_in[0];
    const float* xk = (const float*)d_in[1];
    const float* R  = (const float*)d_in[2];
    float* out      = (float*)d_out;

    cudaFuncSetAttribute(rotary_kernel,
                         cudaFuncAttributeMaxDynamicSharedMemorySize, SMEM_TOTAL);
    dim3 grid(SEQ_LEN, 2);
    rotary_kernel<<<grid, THREADS, SMEM_TOTAL>>>(xq, xk, R, out);
}

// round 12
// speedup vs baseline: 1.2724x; 1.2724x over previous
#include <cuda_runtime.h>
#include <cuda_bf16.h>

// Shapes:
//   xq      [1, 8, 128, 128]  f32
//   xk      [1, 1, 128, 128]  f32
//   rot_mat [1, 128, 128, 128] f32
// out[n,s,d] = sum_h x[n,s,h] * R[s,h,d];  out = concat(xq_out, xk_out)

#define SEQ_LEN   128
#define HEAD_DIM  128
#define N_HEADS   9
#define THREADS   256
#define D_Q       32          // d quarter per CTA  (gridDim.y = 4)
#define N_PHASE   16          // h split into 16 ranges of 8

// Static smem:
//   xs2  [9][128] u64 replicated {v,v}       = 9216 B
//   part [16][9][32] f32                     = 18432 B    -> 27.6 KB total, 3 CTAs/SM

__device__ __forceinline__ unsigned long long ffma2(unsigned long long a,
                                                    unsigned long long b,
                                                    unsigned long long c) {
    unsigned long long d;
    asm("fma.rn.f32x2 %0, %1, %2, %3;" : "=l"(d) : "l"(a), "l"(b), "l"(c));
    return d;
}

__device__ __forceinline__ unsigned long long pack2(float lo, float hi) {
    unsigned long long d;
    asm("mov.b64 %0, {%1, %2};" : "=l"(d) : "f"(lo), "f"(hi));
    return d;
}

__global__ void __launch_bounds__(THREADS, 3)
rotary_kernel(const float* __restrict__ xq,
              const float* __restrict__ xk,
              const float* __restrict__ R,
              float* __restrict__ out)
{
    __shared__ __align__(16) unsigned long long xs2[N_HEADS * HEAD_DIM]; // 9216 B
    __shared__ __align__(16) float part[N_PHASE][N_HEADS][D_Q];          // 18432 B

    const int s    = blockIdx.x;
    const int dq   = blockIdx.y;          // d quarter (0..3)
    const int tid  = threadIdx.x;
    const int lane = tid & 31;
    const int w    = tid >> 5;            // 0..7

    const int ng     = w >> 2;            // 0: heads 0..4, 1: heads 5..8
    const int hr     = w & 3;             // h super-range (32 rows)
    const int d4l    = lane & 7;          // float4 col within quarter (0..7)
    const int h_lane = lane >> 3;         // 0..3 sub-range (8 rows)
    const int hbase  = hr * 32 + h_lane * 8;
    const int nbase  = ng * 5;
    const int NH     = ng ? 4 : 5;

    // ---- 1) Front-batch 8 LDG.128 of this thread's R slice (MLP = 8) ----
    const float4* __restrict__ R4 =
        reinterpret_cast<const float4*>(R + (size_t)s * HEAD_DIM * HEAD_DIM);

    float4 rv[8];
#pragma unroll
    for (int i = 0; i < 8; i++)
        rv[i] = R4[(hbase + i) * 32 + dq * 8 + d4l];

    // ---- 2) Stage x rows (overlaps the R load latency) ----
    for (int idx = tid; idx < N_HEADS * HEAD_DIM; idx += THREADS) {
        const int n = idx >> 7;
        const int h = idx & 127;
        float v;
        if (n < 8)
            v = xq[n * (SEQ_LEN * HEAD_DIM) + s * HEAD_DIM + h];
        else
            v = xk[s * HEAD_DIM + h];
        const unsigned long long u = (unsigned long long)__float_as_uint(v);
        xs2[idx] = (u << 32) | u;   // replicated {v,v} for fma.rn.f32x2
    }
    __syncthreads();

    // ---- 3) Accumulate: 8 h x (4|5) heads x 2 ffma2 ----
    unsigned long long a0[5], a1[5];
#pragma unroll
    for (int j = 0; j < 5; j++) { a0[j] = 0ull; a1[j] = 0ull; }

#pragma unroll
    for (int i = 0; i < 8; i++) {
        const int h = hbase + i;
        const unsigned long long r01 = pack2(rv[i].x, rv[i].y);
        const unsigned long long r23 = pack2(rv[i].z, rv[i].w);
#pragma unroll
        for (int j = 0; j < 5; j++) {
            if (j < NH) {
                const unsigned long long xv = xs2[(nbase + j) * HEAD_DIM + h];
                a0[j] = ffma2(xv, r01, a0[j]);
                a1[j] = ffma2(xv, r23, a1[j]);
            }
        }
    }

    // ---- 4) Per h-range partials ----
    const int pidx = hr * 4 + h_lane;     // 0..15
#pragma unroll
    for (int j = 0; j < 5; j++) {
        if (j < NH) {
            const float2 lo = *reinterpret_cast<const float2*>(&a0[j]);
            const float2 hi = *reinterpret_cast<const float2*>(&a1[j]);
            *reinterpret_cast<float4*>(&part[pidx][nbase + j][d4l * 4]) =
                make_float4(lo.x, lo.y, hi.x, hi.y);
        }
    }
    __syncthreads();

    // ---- 5) Reduce 16 partials, store (coalesced over d) ----
    for (int idx = tid; idx < N_HEADS * D_Q; idx += THREADS) {
        const int n = idx >> 5;           // idx / 32
        const int d = idx & 31;           // idx % 32
        float sum = 0.f;
#pragma unroll
        for (int p = 0; p < N_PHASE; p++)
            sum += part[p][n][d];
        out[n * (SEQ_LEN * HEAD_DIM) + s * HEAD_DIM + dq * D_Q + d] = sum;
    }
}

extern "C" void kernel_launch(void* const* d_in, const int* in_sizes, int n_in,
                              void* d_out, int out_size)
{
    const float* xq = (const float*)d_in[0];
    const float* xk = (const float*)d_in[1];
    const float* R  = (const float*)d_in[2];
    float* out      = (float*)d_out;

    dim3 grid(SEQ_LEN, 4);
    rotary_kernel<<<grid, THREADS>>>(xq, xk, R, out);
}

// round 14
// speedup vs baseline: 1.3346x; 1.0489x over previous
#include <cuda_runtime.h>
#include <cuda_bf16.h>

// Shapes:
//   xq      [1, 8, 128, 128]  f32
//   xk      [1, 1, 128, 128]  f32
//   rot_mat [1, 128, 128, 128] f32
// out[n,s,d] = sum_h x[n,s,h] * R[s,h,d];  out = concat(xq_out, xk_out)

#define SEQ_LEN   128
#define HEAD_DIM  128
#define N_HEADS   9
#define THREADS   256
#define D_HALF    64

__device__ __forceinline__ unsigned long long ffma2(unsigned long long a,
                                                    unsigned long long b,
                                                    unsigned long long c) {
    unsigned long long d;
    asm("fma.rn.f32x2 %0, %1, %2, %3;" : "=l"(d) : "l"(a), "l"(b), "l"(c));
    return d;
}

__device__ __forceinline__ unsigned long long pack2(float lo, float hi) {
    unsigned long long d;
    asm("mov.b64 %0, {%1, %2};" : "=l"(d) : "f"(lo), "f"(hi));
    return d;
}

__global__ void __launch_bounds__(THREADS, 2)
rotary_kernel(const float* __restrict__ xq,
              const float* __restrict__ xk,
              const float* __restrict__ R,
              float* __restrict__ out)
{
    // Only smem: 8 h-partials for the final cross-warp reduce. 18 KB.
    __shared__ __align__(16) float part[8][N_HEADS][D_HALF];

    const int s    = blockIdx.x;
    const int dh   = blockIdx.y;          // d half (0/1)
    const int tid  = threadIdx.x;
    const int lane = tid & 31;
    const int w    = tid >> 5;

    const int ng    = w >> 2;             // 0: heads 0..4, 1: heads 5..8
    const int hr    = w & 3;              // h range of 32 rows
    const int d4l   = lane & 15;          // float4 col within half (0..15)
    const int hp    = lane >> 4;          // h phase (0/1): 16 rows each
    const int nbase = ng * 5;
    const int NH    = ng ? 4 : 5;

    // ---- 1) Front-batch 16 R-LDG.128 (MLP = 16) ----
    const float4* __restrict__ R4 =
        reinterpret_cast<const float4*>(R + (size_t)s * HEAD_DIM * HEAD_DIM);

    float4 rv[16];
#pragma unroll
    for (int i = 0; i < 16; i++)
        rv[i] = R4[(hr * 32 + hp * 16 + i) * 32 + dh * 16 + d4l];

    // ---- 2) x in registers: lane holds x[n][s][hr*32 + lane] for its heads ----
    const int hx = hr * 32 + lane;        // 32 consecutive h per warp (coalesced)
    float xreg[5];
#pragma unroll
    for (int j = 0; j < 5; j++) {
        if (j < NH) {
            const int n = nbase + j;
            xreg[j] = (n < 8) ? xq[n * (SEQ_LEN * HEAD_DIM) + s * HEAD_DIM + hx]
                              : xk[s * HEAD_DIM + hx];
        }
    }

    // ---- 3) Accumulate: 16 h x heads, xv via warp shuffle broadcast ----
    unsigned long long a0[5], a1[5];
#pragma unroll
    for (int j = 0; j < 5; j++) { a0[j] = 0ull; a1[j] = 0ull; }

#pragma unroll
    for (int hh = 0; hh < 16; hh++) {
        const int src = hp * 16 + hh;     // source lane holding this h's x
        const unsigned long long r01 = pack2(rv[hh].x, rv[hh].y);
        const unsigned long long r23 = pack2(rv[hh].z, rv[hh].w);
#pragma unroll
        for (int j = 0; j < 5; j++) {
            if (j < NH) {
                const float xv = __shfl_sync(0xffffffffu, xreg[j], src);
                const unsigned long long xx = pack2(xv, xv);
                a0[j] = ffma2(xx, r01, a0[j]);
                a1[j] = ffma2(xx, r23, a1[j]);
            }
        }
    }

    // ---- 4) Partial write + single barrier ----
    const int pidx = hr * 2 + hp;         // 0..7
#pragma unroll
    for (int j = 0; j < 5; j++) {
        if (j < NH) {
            const float2 lo = *reinterpret_cast<const float2*>(&a0[j]);
            const float2 hi = *reinterpret_cast<const float2*>(&a1[j]);
            *reinterpret_cast<float4*>(&part[pidx][nbase + j][d4l * 4]) =
                make_float4(lo.x, lo.y, hi.x, hi.y);
        }
    }
    __syncthreads();

    // ---- 5) Reduce 8 partials, coalesced store ----
    for (int idx = tid; idx < N_HEADS * D_HALF; idx += THREADS) {
        const int n = idx >> 6;
        const int d = idx & 63;
        float sum = 0.f;
#pragma unroll
        for (int p = 0; p < 8; p++)
            sum += part[p][n][d];
        out[n * (SEQ_LEN * HEAD_DIM) + s * HEAD_DIM + dh * D_HALF + d] = sum;
    }
}

extern "C" void kernel_launch(void* const* d_in, const int* in_sizes, int n_in,
                              void* d_out, int out_size)
{
    const float* xq = (const float*)d_in[0];
    const float* xk = (const float*)d_in[1];
    const float* R  = (const float*)d_in[2];
    float* out      = (float*)d_out;

    dim3 grid(SEQ_LEN, 2);
    rotary_kernel<<<grid, THREADS>>>(xq, xk, R, out);
}

// round 16
// speedup vs baseline: 1.3550x; 1.0153x over previous
#include <cuda_runtime.h>
#include <cuda_bf16.h>

// Shapes:
//   xq      [1, 8, 128, 128]  f32
//   xk      [1, 1, 128, 128]  f32
//   rot_mat [1, 128, 128, 128] f32
// out[n,s,d] = sum_h x[n,s,h] * R[s,h,d];  out = concat(xq_out, xk_out)

#define SEQ_LEN   128
#define HEAD_DIM  128
#define N_HEADS   9
#define THREADS   256
#define D_HALF    64
#define N_PHASE   16

__device__ __forceinline__ unsigned long long ffma2(unsigned long long a,
                                                    unsigned long long b,
                                                    unsigned long long c) {
    unsigned long long d;
    asm("fma.rn.f32x2 %0, %1, %2, %3;" : "=l"(d) : "l"(a), "l"(b), "l"(c));
    return d;
}

__global__ void __launch_bounds__(THREADS, 2)
rotary_kernel(const float* __restrict__ xq,
              const float* __restrict__ xk,
              const float* __restrict__ R,
              float* __restrict__ out)
{
    // xs2: x replicated {v,v} for f32x2; part: 16 h-phase partials.
    __shared__ __align__(16) unsigned long long xs2[N_HEADS * HEAD_DIM];   // 9216 B
    __shared__ __align__(16) float part[N_PHASE][N_HEADS][D_HALF];         // 36864 B

    const int s    = blockIdx.x;
    const int dh   = blockIdx.y;            // d half (0/1)
    const int tid  = threadIdx.x;
    const int lane = tid & 31;
    const int w    = tid >> 5;

    const int ng    = w >> 2;               // 0: heads 0..4, 1: heads 5..8
    const int hr    = w & 3;                // 32-row h range
    const int d4l   = lane & 7;             // first float4 col (second = +8)
    const int hs    = lane >> 3;            // 8-row subrange (0..3)
    const int hbase = hr * 32 + hs * 8;
    const int nbase = ng * 5;
    const int NH    = ng ? 4 : 5;

    // ---- 1) Front-batch 16 R loads as ulonglong2 (== float4, zero packs) ----
    const ulonglong2* __restrict__ R2 =
        reinterpret_cast<const ulonglong2*>(R + (size_t)s * HEAD_DIM * HEAD_DIM);
    const int c0 = dh * 16 + d4l;           // global float4 col
    const int c1 = c0 + 8;

    ulonglong2 rA[8], rB[8];
#pragma unroll
    for (int i = 0; i < 8; i++) {
        rA[i] = R2[(hbase + i) * 32 + c0];
        rB[i] = R2[(hbase + i) * 32 + c1];
    }

    // ---- 2) Stage x rows as {v,v} pairs (overlaps R load flight) ----
    for (int idx = tid; idx < N_HEADS * HEAD_DIM; idx += THREADS) {
        const int n = idx >> 7;
        const int h = idx & 127;
        float v;
        if (n < 8)
            v = xq[n * (SEQ_LEN * HEAD_DIM) + s * HEAD_DIM + h];
        else
            v = xk[s * HEAD_DIM + h];
        const unsigned long long u = (unsigned long long)__float_as_uint(v);
        xs2[idx] = (u << 32) | u;
    }
    __syncthreads();

    // ---- 3) Accumulate: per row, per head: 1 LDS.64 + 4 FFMA2 ----
    unsigned long long aA0[5], aA1[5], aB0[5], aB1[5];
#pragma unroll
    for (int j = 0; j < 5; j++) { aA0[j] = aA1[j] = aB0[j] = aB1[j] = 0ull; }

#pragma unroll
    for (int i = 0; i < 8; i++) {
        const unsigned long long* xrow = &xs2[nbase * HEAD_DIM + hbase + i];
#pragma unroll
        for (int j = 0; j < 5; j++) {
            if (j < NH) {
                const unsigned long long xv = xrow[j * HEAD_DIM];
                aA0[j] = ffma2(xv, rA[i].x, aA0[j]);
                aA1[j] = ffma2(xv, rA[i].y, aA1[j]);
                aB0[j] = ffma2(xv, rB[i].x, aB0[j]);
                aB1[j] = ffma2(xv, rB[i].y, aB1[j]);
            }
        }
    }

    // ---- 4) Partials (16 phases), one barrier ----
    const int pidx = hr * 4 + hs;
#pragma unroll
    for (int j = 0; j < 5; j++) {
        if (j < NH) {
            float2 a0 = *reinterpret_cast<const float2*>(&aA0[j]);
            float2 a1 = *reinterpret_cast<const float2*>(&aA1[j]);
            *reinterpret_cast<float4*>(&part[pidx][nbase + j][d4l * 4]) =
                make_float4(a0.x, a0.y, a1.x, a1.y);
            float2 b0 = *reinterpret_cast<const float2*>(&aB0[j]);
            float2 b1 = *reinterpret_cast<const float2*>(&aB1[j]);
            *reinterpret_cast<float4*>(&part[pidx][nbase + j][(d4l + 8) * 4]) =
                make_float4(b0.x, b0.y, b1.x, b1.y);
        }
    }
    __syncthreads();

    // ---- 5) Reduce 16 phases, coalesced store ----
    for (int idx = tid; idx < N_HEADS * D_HALF; idx += THREADS) {
        const int n = idx >> 6;
        const int d = idx & 63;
        float sum = 0.f;
#pragma unroll
        for (int p = 0; p < N_PHASE; p++)
            sum += part[p][n][d];
        out[n * (SEQ_LEN * HEAD_DIM) + s * HEAD_DIM + dh * D_HALF + d] = sum;
    }
}

extern "C" void kernel_launch(void* const* d_in, const int* in_sizes, int n_in,
                              void* d_out, int out_size)
{
    const float* xq = (const float*)d_in[0];
    const float* xk = (const float*)d_in[1];
    const float* R  = (const float*)d_in[2];
    float* out      = (float*)d_out;

    dim3 grid(SEQ_LEN, 2);
    rotary_kernel<<<grid, THREADS>>>(xq, xk, R, out);
}

// round 17
// speedup vs baseline: 1.4549x; 1.0738x over previous
#include <cuda_runtime.h>
#include <cuda_bf16.h>

// Shapes:
//   xq      [1, 8, 128, 128]  f32
//   xk      [1, 1, 128, 128]  f32
//   rot_mat [1, 128, 128, 128] f32
// out[n,s,d] = sum_h x[n,s,h] * R[s,h,d];  out = concat(xq_out, xk_out)

#define SEQ_LEN   128
#define HEAD_DIM  128
#define N_HEADS   9
#define THREADS   256
#define D_HALF    64

__device__ __forceinline__ unsigned long long ffma2(unsigned long long a,
                                                    unsigned long long b,
                                                    unsigned long long c) {
    unsigned long long d;
    asm("fma.rn.f32x2 %0, %1, %2, %3;" : "=l"(d) : "l"(a), "l"(b), "l"(c));
    return d;
}

__device__ __forceinline__ unsigned long long pack2(float v) {
    unsigned long long d;
    asm("mov.b64 %0, {%1, %1};" : "=l"(d) : "f"(v));
    return d;
}

__global__ void __launch_bounds__(THREADS, 2)
rotary_kernel(const float* __restrict__ xq,
              const float* __restrict__ xk,
              const float* __restrict__ R,
              float* __restrict__ out)
{
    // Only smem: 8 h-partials for the single final join. 18 KB.
    __shared__ __align__(16) float part[8][N_HEADS][D_HALF];

    const int s    = blockIdx.x;
    const int dh   = blockIdx.y;          // d half (0/1)
    const int tid  = threadIdx.x;
    const int lane = tid & 31;
    const int w    = tid >> 5;

    const int ng    = w >> 2;             // 0: heads 0..4, 1: heads 5..8
    const int hr    = w & 3;              // 32-row h range
    const int d4l   = lane & 15;          // float4 col within half
    const int hp    = lane >> 4;          // h phase (0/1): 16 rows
    const int nbase = ng * 5;
    const int NH    = ng ? 4 : 5;
    const int hbase = hr * 32 + hp * 16;  // this lane's 16 h rows

    // ---- 1) Front-batch 16 R LDG.128 (d col = dh*16+d4l, rows hbase..+15) ----
    const float4* __restrict__ R4 =
        reinterpret_cast<const float4*>(R + (size_t)s * HEAD_DIM * HEAD_DIM);

    float4 rv[16];
#pragma unroll
    for (int i = 0; i < 16; i++)
        rv[i] = R4[(hbase + i) * 32 + dh * 16 + d4l];

    // ---- 2) Front-batch x as float4: 4 per head, rows hbase..+15 (L1 broadcast) ----
    const float4* __restrict__ xq4 = reinterpret_cast<const float4*>(xq);
    const float4* __restrict__ xk4 = reinterpret_cast<const float4*>(xk);
    const int xcol = hr * 8 + hp * 4;     // float4 index within the 128-float h row

    float4 xr[5][4];
#pragma unroll
    for (int j = 0; j < 5; j++) {
        if (j < NH) {
            const int n = nbase + j;
            const float4* base = (n < 8)
                ? &xq4[n * (SEQ_LEN * 32) + s * 32 + xcol]
                : &xk4[s * 32 + xcol];
#pragma unroll
            for (int k = 0; k < 4; k++)
                xr[j][k] = base[k];
        }
    }

    // ---- 3) Accumulate: 16 h x heads: pack + 2 FFMA2. No barriers, no shfl. ----
    unsigned long long a0[5], a1[5];
#pragma unroll
    for (int j = 0; j < 5; j++) { a0[j] = 0ull; a1[j] = 0ull; }

#pragma unroll
    for (int k = 0; k < 4; k++) {
#pragma unroll
        for (int e = 0; e < 4; e++) {
            const int hh = k * 4 + e;
            const unsigned long long r01 =
                *reinterpret_cast<const unsigned long long*>(&rv[hh].x);
            const unsigned long long r23 =
                *reinterpret_cast<const unsigned long long*>(&rv[hh].z);
#pragma unroll
            for (int j = 0; j < 5; j++) {
                if (j < NH) {
                    const float xf = (e == 0) ? xr[j][k].x
                                   : (e == 1) ? xr[j][k].y
                                   : (e == 2) ? xr[j][k].z
                                              : xr[j][k].w;
                    const unsigned long long xx = pack2(xf);
                    a0[j] = ffma2(xx, r01, a0[j]);
                    a1[j] = ffma2(xx, r23, a1[j]);
                }
            }
        }
    }

    // ---- 4) Partial write + THE single barrier ----
    const int pidx = hr * 2 + hp;         // 0..7
#pragma unroll
    for (int j = 0; j < 5; j++) {
        if (j < NH) {
            const float2 lo = *reinterpret_cast<const float2*>(&a0[j]);
            const float2 hi = *reinterpret_cast<const float2*>(&a1[j]);
            *reinterpret_cast<float4*>(&part[pidx][nbase + j][d4l * 4]) =
                make_float4(lo.x, lo.y, hi.x, hi.y);
        }
    }
    __syncthreads();

    // ---- 5) Reduce 8 partials, coalesced store ----
    for (int idx = tid; idx < N_HEADS * D_HALF; idx += THREADS) {
        const int n = idx >> 6;
        const int d = idx & 63;
        float sum = 0.f;
#pragma unroll
        for (int p = 0; p < 8; p++)
            sum += part[p][n][d];
        out[n * (SEQ_LEN * HEAD_DIM) + s * HEAD_DIM + dh * D_HALF + d] = sum;
    }
}

extern "C" void kernel_launch(void* const* d_in, const int* in_sizes, int n_in,
                              void* d_out, int out_size)
{
    const float* xq = (const float*)d_in[0];
    const float* xk = (const float*)d_in[1];
    const float* R  = (const float*)d_in[2];
    float* out      = (float*)d_out;

    dim3 grid(SEQ_LEN, 2);
    rotary_kernel<<<grid, THREADS>>>(xq, xk, R, out);
}